// round 1
// baseline (speedup 1.0000x reference)
#include <cuda_runtime.h>

// Problem constants
#define BATCH 2048
#define TLEN  4096
#define ALPHA_C 0.95f
#define THETA_C 0.05f

// ---------------------------------------------------------------------------
// Kernel 1: causal convolutions (taps 8/16/32) -> u[b,k,t], k in {0,1,2}
// Each block: 128 threads, one row, 512 t-values (4 per thread).
// u[k][t] = sum_j w_k[j] * x[t-(k-1)+j]  (zero-padded left)
// ---------------------------------------------------------------------------
__global__ void __launch_bounds__(128) conv_kernel(
    const float* __restrict__ x,
    const float* __restrict__ w8,
    const float* __restrict__ w16,
    const float* __restrict__ w32,
    float* __restrict__ u)
{
    __shared__ float xs[512 + 31];     // x[row, tile0-31 .. tile0+511]
    __shared__ float sw8[8], sw16[16], sw32[32];

    const int tid   = threadIdx.x;
    const int tile0 = blockIdx.x * 512;
    const int row   = blockIdx.y;

    if (tid < 8)  sw8[tid]  = w8[tid];
    if (tid < 16) sw16[tid] = w16[tid];
    if (tid < 32) sw32[tid] = w32[tid];

    const float* xrow = x + (size_t)row * TLEN;
    for (int i = tid; i < 512 + 31; i += 128) {
        int t = tile0 - 31 + i;
        xs[i] = (t >= 0) ? xrow[t] : 0.0f;
    }
    __syncthreads();

    // thread covers t0 .. t0+3 ; window xw[i] = x[t0 - 31 + i], i = 0..34
    const int base = tid * 4;
    float xw[35];
#pragma unroll
    for (int i = 0; i < 35; i++) xw[i] = xs[base + i];

    float a8[4]  = {0.f, 0.f, 0.f, 0.f};
    float a16[4] = {0.f, 0.f, 0.f, 0.f};
    float a32[4] = {0.f, 0.f, 0.f, 0.f};

    // u32[t0+i] = sum_j w32[j] * xw[i + j]
#pragma unroll
    for (int j = 0; j < 32; j++) {
        float w = sw32[j];
#pragma unroll
        for (int i = 0; i < 4; i++) a32[i] = fmaf(w, xw[i + j], a32[i]);
    }
    // u16[t0+i] = sum_j w16[j] * x[t0+i-15+j] = xw[16 + i + j]
#pragma unroll
    for (int j = 0; j < 16; j++) {
        float w = sw16[j];
#pragma unroll
        for (int i = 0; i < 4; i++) a16[i] = fmaf(w, xw[16 + i + j], a16[i]);
    }
    // u8[t0+i] = xw[24 + i + j]
#pragma unroll
    for (int j = 0; j < 8; j++) {
        float w = sw8[j];
#pragma unroll
        for (int i = 0; i < 4; i++) a8[i] = fmaf(w, xw[24 + i + j], a8[i]);
    }

    const int t0 = tile0 + base;
    float4* o0 = reinterpret_cast<float4*>(u + ((size_t)row * 3 + 0) * TLEN + t0);
    float4* o1 = reinterpret_cast<float4*>(u + ((size_t)row * 3 + 1) * TLEN + t0);
    float4* o2 = reinterpret_cast<float4*>(u + ((size_t)row * 3 + 2) * TLEN + t0);
    *o0 = make_float4(a8[0],  a8[1],  a8[2],  a8[3]);
    *o1 = make_float4(a16[0], a16[1], a16[2], a16[3]);
    *o2 = make_float4(a32[0], a32[1], a32[2], a32[3]);
}

// ---------------------------------------------------------------------------
// Kernel 2: LIF + winner-take-all scan. One thread per batch row.
// v' = alpha*v + u ; m = v' - theta ; winner = argmax_k m (first index ties)
// spike = (m_winner >= 0) ; winner's v <- m (== v' - theta), others v <- v'
// ---------------------------------------------------------------------------
__global__ void __launch_bounds__(32, 1) scan_kernel(
    const float* __restrict__ u, float* __restrict__ s)
{
    const int b = blockIdx.x * 32 + threadIdx.x;

    const float4* __restrict__ p0 =
        reinterpret_cast<const float4*>(u + ((size_t)b * 3 + 0) * TLEN);
    const float4* __restrict__ p1 =
        reinterpret_cast<const float4*>(u + ((size_t)b * 3 + 1) * TLEN);
    const float4* __restrict__ p2 =
        reinterpret_cast<const float4*>(u + ((size_t)b * 3 + 2) * TLEN);
    float4* __restrict__ q0 =
        reinterpret_cast<float4*>(s + ((size_t)b * 3 + 0) * TLEN);
    float4* __restrict__ q1 =
        reinterpret_cast<float4*>(s + ((size_t)b * 3 + 1) * TLEN);
    float4* __restrict__ q2 =
        reinterpret_cast<float4*>(s + ((size_t)b * 3 + 2) * TLEN);

    float v0 = 0.f, v1 = 0.f, v2 = 0.f;

    float4 a0 = p0[0], a1 = p1[0], a2 = p2[0];

    const int NQ = TLEN / 4;
    for (int it = 0; it < NQ; it++) {
        // prefetch next quad (clamped; clamp is a cheap SEL)
        int nx = (it + 1 < NQ) ? (it + 1) : it;
        float4 n0 = p0[nx], n1 = p1[nx], n2 = p2[nx];

        float4 o0, o1, o2;

#define LIF_STEP(UX0, UX1, UX2, SO0, SO1, SO2)                                 \
        {                                                                      \
            float w0 = fmaf(ALPHA_C, v0, (UX0));                              \
            float w1 = fmaf(ALPHA_C, v1, (UX1));                              \
            float w2 = fmaf(ALPHA_C, v2, (UX2));                              \
            float m0 = w0 - THETA_C;                                          \
            float m1 = w1 - THETA_C;                                          \
            float m2 = w2 - THETA_C;                                          \
            float best = fmaxf(m0, fmaxf(m1, m2));                            \
            bool fire = (best >= 0.0f);                                       \
            bool b0 = (m0 == best);                                           \
            bool b1 = (m1 == best);                                           \
            bool e0 = fire && b0;                                             \
            bool e1 = fire && b1 && !b0;                                      \
            bool e2 = fire && !b0 && !b1;                                     \
            (SO0) = e0 ? 1.0f : 0.0f;                                         \
            (SO1) = e1 ? 1.0f : 0.0f;                                         \
            (SO2) = e2 ? 1.0f : 0.0f;                                         \
            v0 = e0 ? m0 : w0;                                                \
            v1 = e1 ? m1 : w1;                                                \
            v2 = e2 ? m2 : w2;                                                \
        }

        LIF_STEP(a0.x, a1.x, a2.x, o0.x, o1.x, o2.x);
        LIF_STEP(a0.y, a1.y, a2.y, o0.y, o1.y, o2.y);
        LIF_STEP(a0.z, a1.z, a2.z, o0.z, o1.z, o2.z);
        LIF_STEP(a0.w, a1.w, a2.w, o0.w, o1.w, o2.w);
#undef LIF_STEP

        q0[it] = o0;
        q1[it] = o1;
        q2[it] = o2;

        a0 = n0; a1 = n1; a2 = n2;
    }
}

// ---------------------------------------------------------------------------
// Launch: conv fills u (= first half of d_out), scan fills s (= second half).
// Output layout assumed: [u (B*3*T floats)] then [s (B*3*T floats)].
// ---------------------------------------------------------------------------
extern "C" void kernel_launch(void* const* d_in, const int* in_sizes, int n_in,
                              void* d_out, int out_size)
{
    const float* x   = (const float*)d_in[0];
    const float* w8  = (const float*)d_in[1];
    const float* w16 = (const float*)d_in[2];
    const float* w32 = (const float*)d_in[3];

    float* u = (float*)d_out;
    float* s = u + (size_t)BATCH * 3 * TLEN;

    dim3 cgrid(TLEN / 512, BATCH);
    conv_kernel<<<cgrid, 128>>>(x, w8, w16, w32, u);

    scan_kernel<<<BATCH / 32, 32>>>(u, s);
}

// round 2
// speedup vs baseline: 1.4627x; 1.4627x over previous
#include <cuda_runtime.h>

#define BATCH 2048
#define TLEN  4096
#define ALPHA_C 0.95f
#define THETA_C 0.05f
#define CHUNK   512
#define WARMUP  768
#define NCHUNK  (TLEN / CHUNK)      // 8
#define TQ      (TLEN / 4)          // 1024 quads per (b,k)

// Scratch (static __device__ — no allocation)
__device__ float4       g_uT[3 * TQ * BATCH];            // [k][tq][b] : u quads, transposed for scan
__device__ unsigned int g_sp[NCHUNK * 32 * BATCH];       // [c][w][b]  : 16 x 2-bit spike codes per word

// ---------------------------------------------------------------------------
// Kernel 1: causal convs. Block = 32 rows x 32 t.  blockDim (8,32):
// thread (tx,ty) computes row r=ty, t = t0 + tx*4 .. +3, all 3 channels.
// Results staged in smem, then written BOTH as u[b][k][t] (coalesced along t)
// and as g_uT[k][tq][b] (coalesced along b).
// ---------------------------------------------------------------------------
__global__ void __launch_bounds__(256) conv_kernel(
    const float* __restrict__ x,
    const float* __restrict__ w8,
    const float* __restrict__ w16,
    const float* __restrict__ w32,
    float* __restrict__ u)
{
    __shared__ float xs[32][65];        // x[r][t0-31 .. t0+31]
    __shared__ float st[3][32][33];     // [k][t_local][r]
    __shared__ float sw8[8], sw16[16], sw32[32];

    const int tx = threadIdx.x;               // 0..7
    const int ty = threadIdx.y;               // 0..31
    const int tid = ty * 8 + tx;
    const int t0 = blockIdx.x * 32;
    const int b0 = blockIdx.y * 32;

    if (tid < 8)       sw8[tid]       = w8[tid];
    else if (tid < 24) sw16[tid - 8]  = w16[tid - 8];
    else if (tid < 56) sw32[tid - 24] = w32[tid - 24];

    for (int idx = tid; idx < 32 * 63; idx += 256) {
        int r = idx / 63, i = idx % 63;
        int t = t0 - 31 + i;
        xs[r][i] = (t >= 0) ? x[(size_t)(b0 + r) * TLEN + t] : 0.0f;
    }
    __syncthreads();

    // window xw[j] = x[row, t0 + tx*4 - 31 + j], j = 0..34
    float xw[35];
#pragma unroll
    for (int j = 0; j < 35; j++) xw[j] = xs[ty][tx * 4 + j];

    float a8[4]  = {0.f, 0.f, 0.f, 0.f};
    float a16[4] = {0.f, 0.f, 0.f, 0.f};
    float a32[4] = {0.f, 0.f, 0.f, 0.f};

#pragma unroll
    for (int j = 0; j < 32; j++) {
        float w = sw32[j];
#pragma unroll
        for (int i = 0; i < 4; i++) a32[i] = fmaf(w, xw[i + j], a32[i]);
    }
#pragma unroll
    for (int j = 0; j < 16; j++) {
        float w = sw16[j];
#pragma unroll
        for (int i = 0; i < 4; i++) a16[i] = fmaf(w, xw[16 + i + j], a16[i]);
    }
#pragma unroll
    for (int j = 0; j < 8; j++) {
        float w = sw8[j];
#pragma unroll
        for (int i = 0; i < 4; i++) a8[i] = fmaf(w, xw[24 + i + j], a8[i]);
    }

#pragma unroll
    for (int i = 0; i < 4; i++) {
        st[0][tx * 4 + i][ty] = a8[i];
        st[1][tx * 4 + i][ty] = a16[i];
        st[2][tx * 4 + i][ty] = a32[i];
    }
    __syncthreads();

    const int warp = tid / 32;
    const int lane = tid % 32;

    // u[b][k][t]: warp writes one (r,k) pair, 32 consecutive t -> 128B line
    for (int rk = warp; rk < 96; rk += 8) {
        int r = rk / 3, k = rk % 3;
        u[((size_t)(b0 + r) * 3 + k) * TLEN + t0 + lane] = st[k][lane][r];
    }

    // g_uT[k][tq][b] quads: warp writes one (k, tq_local), 32 consecutive b
    for (int task = warp; task < 24; task += 8) {
        int k = task / 8, tql = task % 8;
        float4 v = make_float4(st[k][tql * 4 + 0][lane],
                               st[k][tql * 4 + 1][lane],
                               st[k][tql * 4 + 2][lane],
                               st[k][tql * 4 + 3][lane]);
        g_uT[((size_t)k * TQ + (t0 >> 2) + tql) * BATCH + b0 + lane] = v;
    }
}

// ---------------------------------------------------------------------------
// LIF + WTA step. Returns 2-bit code: 0 = no spike, k+1 = channel k spiked.
// ---------------------------------------------------------------------------
__device__ __forceinline__ int lif_step(float u0, float u1, float u2,
                                        float& v0, float& v1, float& v2)
{
    float w0 = fmaf(ALPHA_C, v0, u0);
    float w1 = fmaf(ALPHA_C, v1, u1);
    float w2 = fmaf(ALPHA_C, v2, u2);
    float m0 = w0 - THETA_C;
    float m1 = w1 - THETA_C;
    float m2 = w2 - THETA_C;
    float best = fmaxf(m0, fmaxf(m1, m2));
    bool fire = (best >= 0.0f);
    bool t0 = (m0 == best);
    bool t1 = (m1 == best);
    bool e0 = fire && t0;
    bool e1 = fire && t1 && !t0;
    bool e2 = fire && !t0 && !t1;
    v0 = e0 ? m0 : w0;
    v1 = e1 ? m1 : w1;
    v2 = e2 ? m2 : w2;
    return e0 ? 1 : (e1 ? 2 : (e2 ? 3 : 0));
}

// ---------------------------------------------------------------------------
// Kernel 2: chunked LIF scan. One thread per (batch row, chunk).
// Warm-up WARMUP steps from v=0 (contraction makes state exact to ~1e-12),
// then 512 chunk steps emitting 2-bit codes packed 16/word.
// Reads g_uT coalesced (warp = 32 consecutive b). Writes 2MB packed codes.
// ---------------------------------------------------------------------------
__global__ void __launch_bounds__(32) scan_kernel()
{
    const int b = blockIdx.x * 32 + threadIdx.x;
    const int c = blockIdx.y;

    float v0 = 0.f, v1 = 0.f, v2 = 0.f;

    const int tq_chunk = c * (CHUNK / 4);                 // first chunk quad
    const int tq_start = max(0, tq_chunk - WARMUP / 4);

    const float4* __restrict__ p0 = g_uT + (size_t)0 * TQ * BATCH + b;
    const float4* __restrict__ p1 = g_uT + (size_t)1 * TQ * BATCH + b;
    const float4* __restrict__ p2 = g_uT + (size_t)2 * TQ * BATCH + b;

    // ---- warm-up (no output), software-pipelined by one quad ----
    if (tq_start < tq_chunk) {
        float4 a0 = p0[(size_t)tq_start * BATCH];
        float4 a1 = p1[(size_t)tq_start * BATCH];
        float4 a2 = p2[(size_t)tq_start * BATCH];
        for (int tq = tq_start; tq < tq_chunk; tq++) {
            int nx = tq + 1;
            float4 n0 = p0[(size_t)nx * BATCH];
            float4 n1 = p1[(size_t)nx * BATCH];
            float4 n2 = p2[(size_t)nx * BATCH];
            lif_step(a0.x, a1.x, a2.x, v0, v1, v2);
            lif_step(a0.y, a1.y, a2.y, v0, v1, v2);
            lif_step(a0.z, a1.z, a2.z, v0, v1, v2);
            lif_step(a0.w, a1.w, a2.w, v0, v1, v2);
            a0 = n0; a1 = n1; a2 = n2;
        }
    }

    // ---- chunk: 32 words x 16 steps ----
    float4 a0 = p0[(size_t)tq_chunk * BATCH];
    float4 a1 = p1[(size_t)tq_chunk * BATCH];
    float4 a2 = p2[(size_t)tq_chunk * BATCH];
    for (int w = 0; w < 32; w++) {
        unsigned int word = 0;
#pragma unroll
        for (int q = 0; q < 4; q++) {
            int tq = tq_chunk + w * 4 + q;
            int nx = tq + 1;
            bool last = (nx >= tq_chunk + 128);
            float4 n0, n1, n2;
            if (!last) {
                n0 = p0[(size_t)nx * BATCH];
                n1 = p1[(size_t)nx * BATCH];
                n2 = p2[(size_t)nx * BATCH];
            }
            int sh = 2 * (q * 4);
            word |= (unsigned)lif_step(a0.x, a1.x, a2.x, v0, v1, v2) << (sh + 0);
            word |= (unsigned)lif_step(a0.y, a1.y, a2.y, v0, v1, v2) << (sh + 2);
            word |= (unsigned)lif_step(a0.z, a1.z, a2.z, v0, v1, v2) << (sh + 4);
            word |= (unsigned)lif_step(a0.w, a1.w, a2.w, v0, v1, v2) << (sh + 6);
            if (!last) { a0 = n0; a1 = n1; a2 = n2; }
        }
        g_sp[((size_t)c * 32 + w) * BATCH + b] = word;
    }
}

// ---------------------------------------------------------------------------
// Kernel 3: decode packed 2-bit spike codes -> s[b][k][t] as float4.
// Fully coalesced 128MB-scale write; 2MB broadcast-ish read.
// ---------------------------------------------------------------------------
__global__ void __launch_bounds__(256) decode_kernel(float* __restrict__ s)
{
    const int b = blockIdx.y;
    const int linear = blockIdx.x * 256 + threadIdx.x;    // 0..3071
    const int k  = linear >> 10;                          // 0..2
    const int tq = linear & 1023;                         // quad over t
    const int t0 = tq << 2;

    const int c  = t0 >> 9;                               // chunk
    const int w  = (t0 >> 4) & 31;                        // word in chunk
    const int sh = (t0 & 15) * 2;

    unsigned int word = g_sp[((size_t)c * 32 + w) * BATCH + b];
    unsigned int kk = (unsigned)(k + 1);

    float4 o;
    o.x = (((word >> (sh + 0)) & 3u) == kk) ? 1.0f : 0.0f;
    o.y = (((word >> (sh + 2)) & 3u) == kk) ? 1.0f : 0.0f;
    o.z = (((word >> (sh + 4)) & 3u) == kk) ? 1.0f : 0.0f;
    o.w = (((word >> (sh + 6)) & 3u) == kk) ? 1.0f : 0.0f;

    *reinterpret_cast<float4*>(s + ((size_t)b * 3 + k) * TLEN + t0) = o;
}

// ---------------------------------------------------------------------------
extern "C" void kernel_launch(void* const* d_in, const int* in_sizes, int n_in,
                              void* d_out, int out_size)
{
    const float* x   = (const float*)d_in[0];
    const float* w8  = (const float*)d_in[1];
    const float* w16 = (const float*)d_in[2];
    const float* w32 = (const float*)d_in[3];

    float* u = (float*)d_out;
    float* s = u + (size_t)BATCH * 3 * TLEN;

    conv_kernel<<<dim3(TLEN / 32, BATCH / 32), dim3(8, 32)>>>(x, w8, w16, w32, u);
    scan_kernel<<<dim3(BATCH / 32, NCHUNK), 32>>>();
    decode_kernel<<<dim3(12, BATCH), 256>>>(s);
}

// round 3
// speedup vs baseline: 3.1748x; 2.1705x over previous
#include <cuda_runtime.h>

#define BATCH 2048
#define TLEN  4096
#define ALPHA_C 0.95f
#define THETA_C 0.05f
#define CHUNK   256
#define WARMUP  512
#define NCHUNK  (TLEN / CHUNK)      // 16
#define TQ      (TLEN / 4)          // 1024 quads per (b,k)
#define WQ      (WARMUP / 4)        // 128 warm-up quads
#define CQ      (CHUNK / 4)         // 64 chunk quads

// Scratch (static __device__ — no allocation)
__device__ float4       g_uT[3 * TQ * BATCH];              // [k][tq][b]
__device__ unsigned int g_sp[NCHUNK * (CHUNK / 16) * BATCH]; // [c][word][b], 16x2-bit codes

// ---------------------------------------------------------------------------
// Kernel 1: causal convs. Tile = 32 rows x 64 t. blockDim (16,32) = 512 thr.
// Thread (tx,ty): row ty, t = t0 + tx*4 .. +3, all 3 channels.
// ---------------------------------------------------------------------------
__global__ void __launch_bounds__(512) conv_kernel(
    const float* __restrict__ x,
    const float* __restrict__ w8,
    const float* __restrict__ w16,
    const float* __restrict__ w32,
    float* __restrict__ u)
{
    __shared__ float xs[32][97];        // x[r][t0-32 .. t0+63] at i=0..95
    __shared__ float st[3][64][33];     // [k][t_local][r]
    __shared__ float sw8[8], sw16[16], sw32[32];

    const int tx  = threadIdx.x;              // 0..15
    const int ty  = threadIdx.y;              // 0..31
    const int tid = ty * 16 + tx;
    const int t0  = blockIdx.x * 64;
    const int b0  = blockIdx.y * 32;
    const int warp = tid >> 5;                // 0..15
    const int lane = tid & 31;

    if (tid < 8)       sw8[tid]       = w8[tid];
    else if (tid < 24) sw16[tid - 8]  = w16[tid - 8];
    else if (tid < 56) sw32[tid - 24] = w32[tid - 24];

    // stage x: warp w loads rows 2w, 2w+1; 96 floats per row (3 x 32 lanes)
    {
        const int r0 = warp << 1;
#pragma unroll
        for (int rr = 0; rr < 2; rr++) {
            const float* xrow = x + (size_t)(b0 + r0 + rr) * TLEN;
#pragma unroll
            for (int it = 0; it < 3; it++) {
                int i = (it << 5) + lane;
                int t = t0 - 32 + i;
                xs[r0 + rr][i] = (t >= 0) ? xrow[t] : 0.0f;
            }
        }
    }
    __syncthreads();

    // window xw[j] = x[row, t_base - 31 + j] = xs[ty][tx*4 + 1 + j], j=0..34
    float xw[35];
#pragma unroll
    for (int j = 0; j < 35; j++) xw[j] = xs[ty][(tx << 2) + 1 + j];

    float a8[4]  = {0.f, 0.f, 0.f, 0.f};
    float a16[4] = {0.f, 0.f, 0.f, 0.f};
    float a32[4] = {0.f, 0.f, 0.f, 0.f};

#pragma unroll
    for (int j = 0; j < 32; j++) {
        float w = sw32[j];
#pragma unroll
        for (int i = 0; i < 4; i++) a32[i] = fmaf(w, xw[i + j], a32[i]);
    }
#pragma unroll
    for (int j = 0; j < 16; j++) {
        float w = sw16[j];
#pragma unroll
        for (int i = 0; i < 4; i++) a16[i] = fmaf(w, xw[16 + i + j], a16[i]);
    }
#pragma unroll
    for (int j = 0; j < 8; j++) {
        float w = sw8[j];
#pragma unroll
        for (int i = 0; i < 4; i++) a8[i] = fmaf(w, xw[24 + i + j], a8[i]);
    }

#pragma unroll
    for (int i = 0; i < 4; i++) {
        st[0][(tx << 2) + i][ty] = a8[i];
        st[1][(tx << 2) + i][ty] = a16[i];
        st[2][(tx << 2) + i][ty] = a32[i];
    }
    __syncthreads();

    // u[b][k][t]: 96 (k,r) pairs; warp handles 6; lanes cover 64 t via float2
#pragma unroll
    for (int p = warp; p < 96; p += 16) {
        int k = p >> 5, r = p & 31;
        int tl = lane << 1;
        float2 v = make_float2(st[k][tl][r], st[k][tl + 1][r]);
        *reinterpret_cast<float2*>(
            u + ((size_t)(b0 + r) * 3 + k) * TLEN + t0 + tl) = v;
    }

    // g_uT[k][tq][b]: 48 (k,tql) pairs; warp handles 3; lane = r
#pragma unroll
    for (int p = warp; p < 48; p += 16) {
        int k = p >> 4, tql = p & 15;
        float4 v = make_float4(st[k][(tql << 2) + 0][lane],
                               st[k][(tql << 2) + 1][lane],
                               st[k][(tql << 2) + 2][lane],
                               st[k][(tql << 2) + 3][lane]);
        g_uT[((size_t)k * TQ + (t0 >> 2) + tql) * BATCH + b0 + lane] = v;
    }
}

// ---------------------------------------------------------------------------
// LIF + WTA step — decision logic IDENTICAL to validated rounds 1-2.
// ---------------------------------------------------------------------------
__device__ __forceinline__ int lif_step(float u0, float u1, float u2,
                                        float& v0, float& v1, float& v2)
{
    float w0 = fmaf(ALPHA_C, v0, u0);
    float w1 = fmaf(ALPHA_C, v1, u1);
    float w2 = fmaf(ALPHA_C, v2, u2);
    float m0 = w0 - THETA_C;
    float m1 = w1 - THETA_C;
    float m2 = w2 - THETA_C;
    float best = fmaxf(m0, fmaxf(m1, m2));
    bool fire = (best >= 0.0f);
    bool t0 = (m0 == best);
    bool t1 = (m1 == best);
    bool e0 = fire && t0;
    bool e1 = fire && t1 && !t0;
    bool e2 = fire && !t0 && !t1;
    v0 = e0 ? m0 : w0;
    v1 = e1 ? m1 : w1;
    v2 = e2 ? m2 : w2;
    return e0 ? 1 : (e1 ? 2 : (e2 ? 3 : 0));
}

// ---------------------------------------------------------------------------
// Kernel 2: chunked LIF scan with 4-quad register pipeline.
// One thread per (row, chunk). 128 threads/block, warp = 32 consecutive b.
// ---------------------------------------------------------------------------
__global__ void __launch_bounds__(128) scan_kernel()
{
    const int b = blockIdx.x * 128 + threadIdx.x;
    const int c = blockIdx.y;

    const int gq_chunk = c * CQ;                      // first chunk quad
    const int gq_start = (gq_chunk >= WQ) ? (gq_chunk - WQ) : 0;

    const float4* __restrict__ p0 = g_uT + (size_t)0 * TQ * BATCH + b;
    const float4* __restrict__ p1 = g_uT + (size_t)1 * TQ * BATCH + b;
    const float4* __restrict__ p2 = g_uT + (size_t)2 * TQ * BATCH + b;

    float v0 = 0.f, v1 = 0.f, v2 = 0.f;

    float4 r0[4], r1[4], r2[4];
#pragma unroll
    for (int j = 0; j < 4; j++) {
        size_t o = (size_t)(gq_start + j) * BATCH;
        r0[j] = p0[o]; r1[j] = p1[o]; r2[j] = p2[o];
    }

    // warm-up: groups of 4 quads, discard spikes, keep 12 loads in flight
    for (int g = gq_start; g < gq_chunk; g += 4) {
#pragma unroll
        for (int j = 0; j < 4; j++) {
            float4 a0 = r0[j], a1 = r1[j], a2 = r2[j];
            int nq = g + j + 4;
            if (nq > TQ - 1) nq = TQ - 1;
            size_t o = (size_t)nq * BATCH;
            r0[j] = p0[o]; r1[j] = p1[o]; r2[j] = p2[o];
            lif_step(a0.x, a1.x, a2.x, v0, v1, v2);
            lif_step(a0.y, a1.y, a2.y, v0, v1, v2);
            lif_step(a0.z, a1.z, a2.z, v0, v1, v2);
            lif_step(a0.w, a1.w, a2.w, v0, v1, v2);
        }
    }

    // chunk: 16 groups; each group (4 quads = 16 steps) packs one word
#pragma unroll 1
    for (int g = 0; g < CQ / 4; g++) {
        unsigned int word = 0;
#pragma unroll
        for (int j = 0; j < 4; j++) {
            float4 a0 = r0[j], a1 = r1[j], a2 = r2[j];
            int nq = gq_chunk + (g << 2) + j + 4;
            if (nq > TQ - 1) nq = TQ - 1;
            size_t o = (size_t)nq * BATCH;
            r0[j] = p0[o]; r1[j] = p1[o]; r2[j] = p2[o];
            int sh = j << 3;                      // 4 steps x 2 bits
            word |= (unsigned)lif_step(a0.x, a1.x, a2.x, v0, v1, v2) << (sh + 0);
            word |= (unsigned)lif_step(a0.y, a1.y, a2.y, v0, v1, v2) << (sh + 2);
            word |= (unsigned)lif_step(a0.z, a1.z, a2.z, v0, v1, v2) << (sh + 4);
            word |= (unsigned)lif_step(a0.w, a1.w, a2.w, v0, v1, v2) << (sh + 6);
        }
        g_sp[((size_t)c * (CHUNK / 16) + g) * BATCH + b] = word;
    }
}

// ---------------------------------------------------------------------------
// Kernel 3: decode packed codes -> s[b][k][t] (coalesced float4 writes)
// ---------------------------------------------------------------------------
__global__ void __launch_bounds__(256) decode_kernel(float* __restrict__ s)
{
    const int b = blockIdx.y;
    const int linear = blockIdx.x * 256 + threadIdx.x;    // 0..3071
    const int k  = linear >> 10;                          // 0..2
    const int tq = linear & 1023;
    const int t0 = tq << 2;

    const int c  = t0 >> 8;                               // chunk (256 t)
    const int w  = (t0 >> 4) & (CHUNK / 16 - 1);          // word in chunk
    const int sh = (t0 & 15) * 2;

    unsigned int word = g_sp[((size_t)c * (CHUNK / 16) + w) * BATCH + b];
    unsigned int kk = (unsigned)(k + 1);

    float4 o;
    o.x = (((word >> (sh + 0)) & 3u) == kk) ? 1.0f : 0.0f;
    o.y = (((word >> (sh + 2)) & 3u) == kk) ? 1.0f : 0.0f;
    o.z = (((word >> (sh + 4)) & 3u) == kk) ? 1.0f : 0.0f;
    o.w = (((word >> (sh + 6)) & 3u) == kk) ? 1.0f : 0.0f;

    *reinterpret_cast<float4*>(s + ((size_t)b * 3 + k) * TLEN + t0) = o;
}

// ---------------------------------------------------------------------------
extern "C" void kernel_launch(void* const* d_in, const int* in_sizes, int n_in,
                              void* d_out, int out_size)
{
    const float* x   = (const float*)d_in[0];
    const float* w8  = (const float*)d_in[1];
    const float* w16 = (const float*)d_in[2];
    const float* w32 = (const float*)d_in[3];

    float* u = (float*)d_out;
    float* s = u + (size_t)BATCH * 3 * TLEN;

    conv_kernel<<<dim3(TLEN / 64, BATCH / 32), dim3(16, 32)>>>(x, w8, w16, w32, u);
    scan_kernel<<<dim3(BATCH / 128, NCHUNK), 128>>>();
    decode_kernel<<<dim3(12, BATCH), 256>>>(s);
}

// round 4
// speedup vs baseline: 3.4674x; 1.0922x over previous
#include <cuda_runtime.h>

#define BATCH 2048
#define TLEN  4096
#define ALPHA_C 0.95f
#define THETA_C 0.05f
#define CHUNK   256
#define WARMUP  384
#define NCHUNK  (TLEN / CHUNK)        // 16
#define TQ      (TLEN / 4)            // 1024 quads per (b,k)
#define WQ      (WARMUP / 4)          // 96 warm-up quads
#define CQ      (CHUNK / 4)           // 64 chunk quads

// Scratch (static __device__ — no allocation)
__device__ float4       g_uT[3 * TQ * BATCH];                // [k][tq][b]
__device__ unsigned int g_sp[NCHUNK * (CHUNK / 16) * BATCH]; // [c][word][b]

// ---------------------------------------------------------------------------
// Kernel 1: causal convs. Tile = 32 rows x 64 t. blockDim (8,32) = 256 thr.
// Thread (tx,ty): row ty, t = t0 + tx*8 .. +7, all 3 channels.
// u written DIRECTLY from registers (float4 x2 per channel).
// smem staging only for the g_uT (b-major) transpose.
// ---------------------------------------------------------------------------
__global__ void __launch_bounds__(256) conv_kernel(
    const float* __restrict__ x,
    const float* __restrict__ w8,
    const float* __restrict__ w16,
    const float* __restrict__ w32,
    float* __restrict__ u)
{
    __shared__ float xs[32][97];        // x[r][t0-32 .. t0+63] at i=0..95
    __shared__ float st[3][64][33];     // [k][t_local][r]
    __shared__ float sw8[8], sw16[16], sw32[32];

    const int tx  = threadIdx.x;               // 0..7
    const int ty  = threadIdx.y;               // 0..31
    const int tid = ty * 8 + tx;
    const int t0  = blockIdx.x * 64;
    const int b0  = blockIdx.y * 32;
    const int warp = tid >> 5;                 // 0..7
    const int lane = tid & 31;

    if (tid < 8)       sw8[tid]       = w8[tid];
    else if (tid < 24) sw16[tid - 8]  = w16[tid - 8];
    else if (tid < 56) sw32[tid - 24] = w32[tid - 24];

    // stage x: warp w loads rows 4w..4w+3; 96 floats per row (3 x 32 lanes)
    {
        const int r0 = warp << 2;
#pragma unroll
        for (int rr = 0; rr < 4; rr++) {
            const float* xrow = x + (size_t)(b0 + r0 + rr) * TLEN;
#pragma unroll
            for (int seg = 0; seg < 3; seg++) {
                int i = (seg << 5) + lane;
                int t = t0 - 32 + i;
                xs[r0 + rr][i] = (t >= 0) ? xrow[t] : 0.0f;
            }
        }
    }
    __syncthreads();

    // window xw[j] = x[row, t_base - 31 + j], t_base = t0 + tx*8, j = 0..38
    float xw[39];
#pragma unroll
    for (int j = 0; j < 39; j++) xw[j] = xs[ty][(tx << 3) + 1 + j];

    float a8[8], a16[8], a32[8];
#pragma unroll
    for (int i = 0; i < 8; i++) { a8[i] = 0.f; a16[i] = 0.f; a32[i] = 0.f; }

#pragma unroll
    for (int j = 0; j < 32; j++) {
        float w = sw32[j];
#pragma unroll
        for (int i = 0; i < 8; i++) a32[i] = fmaf(w, xw[i + j], a32[i]);
    }
#pragma unroll
    for (int j = 0; j < 16; j++) {
        float w = sw16[j];
#pragma unroll
        for (int i = 0; i < 8; i++) a16[i] = fmaf(w, xw[16 + i + j], a16[i]);
    }
#pragma unroll
    for (int j = 0; j < 8; j++) {
        float w = sw8[j];
#pragma unroll
        for (int i = 0; i < 8; i++) a8[i] = fmaf(w, xw[24 + i + j], a8[i]);
    }

    // direct coalesced u stores: row b0+ty, channel k, t = t0+tx*8 .. +7
    {
        float* ub = u + ((size_t)(b0 + ty) * 3) * TLEN + t0 + (tx << 3);
        reinterpret_cast<float4*>(ub + 0 * TLEN)[0] = make_float4(a8[0],  a8[1],  a8[2],  a8[3]);
        reinterpret_cast<float4*>(ub + 0 * TLEN)[1] = make_float4(a8[4],  a8[5],  a8[6],  a8[7]);
        reinterpret_cast<float4*>(ub + 1 * TLEN)[0] = make_float4(a16[0], a16[1], a16[2], a16[3]);
        reinterpret_cast<float4*>(ub + 1 * TLEN)[1] = make_float4(a16[4], a16[5], a16[6], a16[7]);
        reinterpret_cast<float4*>(ub + 2 * TLEN)[0] = make_float4(a32[0], a32[1], a32[2], a32[3]);
        reinterpret_cast<float4*>(ub + 2 * TLEN)[1] = make_float4(a32[4], a32[5], a32[6], a32[7]);
    }

    // stage for transpose
#pragma unroll
    for (int i = 0; i < 8; i++) {
        st[0][(tx << 3) + i][ty] = a8[i];
        st[1][(tx << 3) + i][ty] = a16[i];
        st[2][(tx << 3) + i][ty] = a32[i];
    }
    __syncthreads();

    // g_uT[k][tq][b]: 48 (k,tql) tasks; warp handles 6; lane = r (stride-1 LDS)
#pragma unroll
    for (int p = warp; p < 48; p += 8) {
        int k = p >> 4, tql = p & 15;
        float4 v = make_float4(st[k][(tql << 2) + 0][lane],
                               st[k][(tql << 2) + 1][lane],
                               st[k][(tql << 2) + 2][lane],
                               st[k][(tql << 2) + 3][lane]);
        g_uT[((size_t)k * TQ + (t0 >> 2) + tql) * BATCH + b0 + lane] = v;
    }
}

// ---------------------------------------------------------------------------
// LIF + WTA step — decision logic IDENTICAL to validated rounds 1-3.
// ---------------------------------------------------------------------------
__device__ __forceinline__ int lif_step(float u0, float u1, float u2,
                                        float& v0, float& v1, float& v2)
{
    float w0 = fmaf(ALPHA_C, v0, u0);
    float w1 = fmaf(ALPHA_C, v1, u1);
    float w2 = fmaf(ALPHA_C, v2, u2);
    float m0 = w0 - THETA_C;
    float m1 = w1 - THETA_C;
    float m2 = w2 - THETA_C;
    float best = fmaxf(m0, fmaxf(m1, m2));
    bool fire = (best >= 0.0f);
    bool t0 = (m0 == best);
    bool t1 = (m1 == best);
    bool e0 = fire && t0;
    bool e1 = fire && t1 && !t0;
    bool e2 = fire && !t0 && !t1;
    v0 = e0 ? m0 : w0;
    v1 = e1 ? m1 : w1;
    v2 = e2 ? m2 : w2;
    return e0 ? 1 : (e1 ? 2 : (e2 ? 3 : 0));
}

// ---------------------------------------------------------------------------
// Kernel 2: chunked LIF scan with 4-quad register pipeline.
// ---------------------------------------------------------------------------
__global__ void __launch_bounds__(128) scan_kernel()
{
    const int b = blockIdx.x * 128 + threadIdx.x;
    const int c = blockIdx.y;

    const int gq_chunk = c * CQ;
    const int gq_start = (gq_chunk >= WQ) ? (gq_chunk - WQ) : 0;

    const float4* __restrict__ p0 = g_uT + (size_t)0 * TQ * BATCH + b;
    const float4* __restrict__ p1 = g_uT + (size_t)1 * TQ * BATCH + b;
    const float4* __restrict__ p2 = g_uT + (size_t)2 * TQ * BATCH + b;

    float v0 = 0.f, v1 = 0.f, v2 = 0.f;

    float4 r0[4], r1[4], r2[4];
#pragma unroll
    for (int j = 0; j < 4; j++) {
        size_t o = (size_t)(gq_start + j) * BATCH;
        r0[j] = p0[o]; r1[j] = p1[o]; r2[j] = p2[o];
    }

    // warm-up: groups of 4 quads, discard spikes, keep 12 loads in flight
    for (int g = gq_start; g < gq_chunk; g += 4) {
#pragma unroll
        for (int j = 0; j < 4; j++) {
            float4 a0 = r0[j], a1 = r1[j], a2 = r2[j];
            int nq = g + j + 4;
            if (nq > TQ - 1) nq = TQ - 1;
            size_t o = (size_t)nq * BATCH;
            r0[j] = p0[o]; r1[j] = p1[o]; r2[j] = p2[o];
            lif_step(a0.x, a1.x, a2.x, v0, v1, v2);
            lif_step(a0.y, a1.y, a2.y, v0, v1, v2);
            lif_step(a0.z, a1.z, a2.z, v0, v1, v2);
            lif_step(a0.w, a1.w, a2.w, v0, v1, v2);
        }
    }

    // chunk: 16 groups; each group (4 quads = 16 steps) packs one word
#pragma unroll 1
    for (int g = 0; g < CQ / 4; g++) {
        unsigned int word = 0;
#pragma unroll
        for (int j = 0; j < 4; j++) {
            float4 a0 = r0[j], a1 = r1[j], a2 = r2[j];
            int nq = gq_chunk + (g << 2) + j + 4;
            if (nq > TQ - 1) nq = TQ - 1;
            size_t o = (size_t)nq * BATCH;
            r0[j] = p0[o]; r1[j] = p1[o]; r2[j] = p2[o];
            int sh = j << 3;
            word |= (unsigned)lif_step(a0.x, a1.x, a2.x, v0, v1, v2) << (sh + 0);
            word |= (unsigned)lif_step(a0.y, a1.y, a2.y, v0, v1, v2) << (sh + 2);
            word |= (unsigned)lif_step(a0.z, a1.z, a2.z, v0, v1, v2) << (sh + 4);
            word |= (unsigned)lif_step(a0.w, a1.w, a2.w, v0, v1, v2) << (sh + 6);
        }
        g_sp[((size_t)c * (CHUNK / 16) + g) * BATCH + b] = word;
    }
}

// ---------------------------------------------------------------------------
// Kernel 3: decode packed codes -> s[b][k][t] (coalesced float4 writes)
// ---------------------------------------------------------------------------
__global__ void __launch_bounds__(256) decode_kernel(float* __restrict__ s)
{
    const int b = blockIdx.y;
    const int linear = blockIdx.x * 256 + threadIdx.x;    // 0..3071
    const int k  = linear >> 10;
    const int tq = linear & 1023;
    const int t0 = tq << 2;

    const int c  = t0 >> 8;                               // chunk (256 t)
    const int w  = (t0 >> 4) & (CHUNK / 16 - 1);          // word in chunk
    const int sh = (t0 & 15) * 2;

    unsigned int word = g_sp[((size_t)c * (CHUNK / 16) + w) * BATCH + b];
    unsigned int kk = (unsigned)(k + 1);

    float4 o;
    o.x = (((word >> (sh + 0)) & 3u) == kk) ? 1.0f : 0.0f;
    o.y = (((word >> (sh + 2)) & 3u) == kk) ? 1.0f : 0.0f;
    o.z = (((word >> (sh + 4)) & 3u) == kk) ? 1.0f : 0.0f;
    o.w = (((word >> (sh + 6)) & 3u) == kk) ? 1.0f : 0.0f;

    *reinterpret_cast<float4*>(s + ((size_t)b * 3 + k) * TLEN + t0) = o;
}

// ---------------------------------------------------------------------------
extern "C" void kernel_launch(void* const* d_in, const int* in_sizes, int n_in,
                              void* d_out, int out_size)
{
    const float* x   = (const float*)d_in[0];
    const float* w8  = (const float*)d_in[1];
    const float* w16 = (const float*)d_in[2];
    const float* w32 = (const float*)d_in[3];

    float* u = (float*)d_out;
    float* s = u + (size_t)BATCH * 3 * TLEN;

    conv_kernel<<<dim3(TLEN / 64, BATCH / 32), dim3(8, 32)>>>(x, w8, w16, w32, u);
    scan_kernel<<<dim3(BATCH / 128, NCHUNK), 128>>>();
    decode_kernel<<<dim3(12, BATCH), 256>>>(s);
}

// round 5
// speedup vs baseline: 4.0674x; 1.1730x over previous
#include <cuda_runtime.h>

#define BATCH 2048
#define TLEN  4096
#define ALPHA_C 0.95f
#define THETA_C 0.05f

// scan geometry
#define ROWS_PB 64                  // batch rows per block
#define SEG     512                 // output timesteps per block
#define NSEG    (TLEN / SEG)        // 8
#define WU      384                 // warm-up steps (alpha^384 ~ 3e-9)
#define TILE    32                  // timesteps per smem tile
#define RPAD    65                  // row stride in smem (65 = 1 mod 32 -> conflict-free)

// ---------------------------------------------------------------------------
// Kernel 1: causal convs. Tile = 32 rows x 64 t. blockDim (8,32) = 256 thr.
// Thread (tx,ty): row ty, t = t0 + tx*8 .. +7, all 3 channels.
// Writes u[b][k][t] directly from registers (coalesced float4).
// ---------------------------------------------------------------------------
__global__ void __launch_bounds__(256) conv_kernel(
    const float* __restrict__ x,
    const float* __restrict__ w8,
    const float* __restrict__ w16,
    const float* __restrict__ w32,
    float* __restrict__ u)
{
    __shared__ float xs[32][97];        // x[r][t0-32 .. t0+63]
    __shared__ float sw8[8], sw16[16], sw32[32];

    const int tx  = threadIdx.x;               // 0..7
    const int ty  = threadIdx.y;               // 0..31
    const int tid = ty * 8 + tx;
    const int t0  = blockIdx.x * 64;
    const int b0  = blockIdx.y * 32;
    const int warp = tid >> 5;
    const int lane = tid & 31;

    if (tid < 8)       sw8[tid]       = w8[tid];
    else if (tid < 24) sw16[tid - 8]  = w16[tid - 8];
    else if (tid < 56) sw32[tid - 24] = w32[tid - 24];

    {
        const int r0 = warp << 2;
#pragma unroll
        for (int rr = 0; rr < 4; rr++) {
            const float* xrow = x + (size_t)(b0 + r0 + rr) * TLEN;
#pragma unroll
            for (int seg = 0; seg < 3; seg++) {
                int i = (seg << 5) + lane;
                int t = t0 - 32 + i;
                xs[r0 + rr][i] = (t >= 0) ? xrow[t] : 0.0f;
            }
        }
    }
    __syncthreads();

    float xw[39];
#pragma unroll
    for (int j = 0; j < 39; j++) xw[j] = xs[ty][(tx << 3) + 1 + j];

    float a8[8], a16[8], a32[8];
#pragma unroll
    for (int i = 0; i < 8; i++) { a8[i] = 0.f; a16[i] = 0.f; a32[i] = 0.f; }

#pragma unroll
    for (int j = 0; j < 32; j++) {
        float w = sw32[j];
#pragma unroll
        for (int i = 0; i < 8; i++) a32[i] = fmaf(w, xw[i + j], a32[i]);
    }
#pragma unroll
    for (int j = 0; j < 16; j++) {
        float w = sw16[j];
#pragma unroll
        for (int i = 0; i < 8; i++) a16[i] = fmaf(w, xw[16 + i + j], a16[i]);
    }
#pragma unroll
    for (int j = 0; j < 8; j++) {
        float w = sw8[j];
#pragma unroll
        for (int i = 0; i < 8; i++) a8[i] = fmaf(w, xw[24 + i + j], a8[i]);
    }

    float* ub = u + ((size_t)(b0 + ty) * 3) * TLEN + t0 + (tx << 3);
    reinterpret_cast<float4*>(ub + 0 * TLEN)[0] = make_float4(a8[0],  a8[1],  a8[2],  a8[3]);
    reinterpret_cast<float4*>(ub + 0 * TLEN)[1] = make_float4(a8[4],  a8[5],  a8[6],  a8[7]);
    reinterpret_cast<float4*>(ub + 1 * TLEN)[0] = make_float4(a16[0], a16[1], a16[2], a16[3]);
    reinterpret_cast<float4*>(ub + 1 * TLEN)[1] = make_float4(a16[4], a16[5], a16[6], a16[7]);
    reinterpret_cast<float4*>(ub + 2 * TLEN)[0] = make_float4(a32[0], a32[1], a32[2], a32[3]);
    reinterpret_cast<float4*>(ub + 2 * TLEN)[1] = make_float4(a32[4], a32[5], a32[6], a32[7]);
}

// ---------------------------------------------------------------------------
// LIF + WTA step — decision logic IDENTICAL to validated rounds 1-4.
// Emits spike floats.
// ---------------------------------------------------------------------------
__device__ __forceinline__ void lif_step_s(float u0, float u1, float u2,
                                           float& v0, float& v1, float& v2,
                                           float& s0, float& s1, float& s2)
{
    float w0 = fmaf(ALPHA_C, v0, u0);
    float w1 = fmaf(ALPHA_C, v1, u1);
    float w2 = fmaf(ALPHA_C, v2, u2);
    float m0 = w0 - THETA_C;
    float m1 = w1 - THETA_C;
    float m2 = w2 - THETA_C;
    float best = fmaxf(m0, fmaxf(m1, m2));
    bool fire = (best >= 0.0f);
    bool t0 = (m0 == best);
    bool t1 = (m1 == best);
    bool e0 = fire && t0;
    bool e1 = fire && t1 && !t0;
    bool e2 = fire && !t0 && !t1;
    s0 = e0 ? 1.0f : 0.0f;
    s1 = e1 ? 1.0f : 0.0f;
    s2 = e2 ? 1.0f : 0.0f;
    v0 = e0 ? m0 : w0;
    v1 = e1 ? m1 : w1;
    v2 = e2 ? m2 : w2;
}

// ---------------------------------------------------------------------------
// Kernel 2: fused transpose + LIF scan + spike write.
// Block = 64 threads = 64 batch rows; blockIdx.y = 512-t output segment.
// Per 32-t tile: batched LDG.128 (next tile) -> compute (smem, in-place s)
// -> STS next tile -> coalesced STG of s.
// ---------------------------------------------------------------------------
__global__ void __launch_bounds__(64, 4) scan_fused(
    const float* __restrict__ u, float* __restrict__ s)
{
    __shared__ float buf[2][3][TILE][RPAD];   // [slot][k][t][row]

    const int tid = threadIdx.x;              // row within group, 0..63
    const int b0  = blockIdx.x * ROWS_PB;
    const int seg = blockIdx.y;

    const int t_out0  = seg * SEG;
    const int t_begin = (seg == 0) ? 0 : (t_out0 - WU);
    const int ntiles  = (t_out0 + SEG - t_begin) / TILE;   // 16 or 28
    const int wu_tiles = (t_out0 - t_begin) / TILE;        // 0 or 12

    // per-thread load set: p = tid + 64*i, i<24 ; p -> (k, row, f4)
    // k = p>>9, row = (p>>3)&63, f4 = p&7 ; loads u[b0+row][k][tt + 4*f4 ..+3]

    float4 tmp[24];

    // prologue: load + stage tile 0
#pragma unroll
    for (int i = 0; i < 24; i++) {
        int p = tid + (i << 6);
        int k = p >> 9, row = (p >> 3) & 63, f4 = p & 7;
        tmp[i] = *reinterpret_cast<const float4*>(
            u + ((size_t)(b0 + row) * 3 + k) * TLEN + t_begin + (f4 << 2));
    }
#pragma unroll
    for (int i = 0; i < 24; i++) {
        int p = tid + (i << 6);
        int k = p >> 9, row = (p >> 3) & 63, f4 = p & 7;
        buf[0][k][(f4 << 2) + 0][row] = tmp[i].x;
        buf[0][k][(f4 << 2) + 1][row] = tmp[i].y;
        buf[0][k][(f4 << 2) + 2][row] = tmp[i].z;
        buf[0][k][(f4 << 2) + 3][row] = tmp[i].w;
    }
    __syncthreads();

    float v0 = 0.f, v1 = 0.f, v2 = 0.f;

#pragma unroll 1
    for (int ti = 0; ti < ntiles; ti++) {
        const int cur = ti & 1;
        const bool has_next = (ti + 1 < ntiles);
        const bool emit = (ti >= wu_tiles);

        // issue next tile's loads (LDGs in flight during compute)
        if (has_next) {
            int tt = t_begin + (ti + 1) * TILE;
#pragma unroll
            for (int i = 0; i < 24; i++) {
                int p = tid + (i << 6);
                int k = p >> 9, row = (p >> 3) & 63, f4 = p & 7;
                tmp[i] = *reinterpret_cast<const float4*>(
                    u + ((size_t)(b0 + row) * 3 + k) * TLEN + tt + (f4 << 2));
            }
        }

        // compute 32 steps; write spikes in place (output tiles only)
        if (emit) {
#pragma unroll
            for (int t = 0; t < TILE; t++) {
                float u0 = buf[cur][0][t][tid];
                float u1 = buf[cur][1][t][tid];
                float u2 = buf[cur][2][t][tid];
                float s0, s1, s2;
                lif_step_s(u0, u1, u2, v0, v1, v2, s0, s1, s2);
                buf[cur][0][t][tid] = s0;
                buf[cur][1][t][tid] = s1;
                buf[cur][2][t][tid] = s2;
            }
        } else {
#pragma unroll
            for (int t = 0; t < TILE; t++) {
                float u0 = buf[cur][0][t][tid];
                float u1 = buf[cur][1][t][tid];
                float u2 = buf[cur][2][t][tid];
                float s0, s1, s2;
                lif_step_s(u0, u1, u2, v0, v1, v2, s0, s1, s2);
            }
        }

        // stage next tile into the other buffer
        if (has_next) {
            const int nxt = cur ^ 1;
#pragma unroll
            for (int i = 0; i < 24; i++) {
                int p = tid + (i << 6);
                int k = p >> 9, row = (p >> 3) & 63, f4 = p & 7;
                buf[nxt][k][(f4 << 2) + 0][row] = tmp[i].x;
                buf[nxt][k][(f4 << 2) + 1][row] = tmp[i].y;
                buf[nxt][k][(f4 << 2) + 2][row] = tmp[i].z;
                buf[nxt][k][(f4 << 2) + 3][row] = tmp[i].w;
            }
        }
        __syncthreads();

        // coalesced spike store from smem
        if (emit) {
            int tt = t_begin + ti * TILE;
#pragma unroll
            for (int i = 0; i < 24; i++) {
                int p = tid + (i << 6);
                int k = p >> 9, row = (p >> 3) & 63, f4 = p & 7;
                float4 o;
                o.x = buf[cur][k][(f4 << 2) + 0][row];
                o.y = buf[cur][k][(f4 << 2) + 1][row];
                o.z = buf[cur][k][(f4 << 2) + 2][row];
                o.w = buf[cur][k][(f4 << 2) + 3][row];
                *reinterpret_cast<float4*>(
                    s + ((size_t)(b0 + row) * 3 + k) * TLEN + tt + (f4 << 2)) = o;
            }
            __syncthreads();   // protect buf[cur] before it is re-staged (ti+2)
        }
    }
}

// ---------------------------------------------------------------------------
extern "C" void kernel_launch(void* const* d_in, const int* in_sizes, int n_in,
                              void* d_out, int out_size)
{
    const float* x   = (const float*)d_in[0];
    const float* w8  = (const float*)d_in[1];
    const float* w16 = (const float*)d_in[2];
    const float* w32 = (const float*)d_in[3];

    float* u = (float*)d_out;
    float* s = u + (size_t)BATCH * 3 * TLEN;

    conv_kernel<<<dim3(TLEN / 64, BATCH / 32), dim3(8, 32)>>>(x, w8, w16, w32, u);
    scan_fused<<<dim3(BATCH / ROWS_PB, NSEG), 64>>>(u, s);
}

// round 6
// speedup vs baseline: 4.8221x; 1.1855x over previous
#include <cuda_runtime.h>
#include <cstdint>

#define BATCH 2048
#define TLEN  4096
#define ALPHA_C 0.95f
#define THETA_C 0.05f

// scan geometry
#define ROWS_PB 64                  // batch rows per block
#define SEG     512                 // output timesteps per block
#define NSEG    (TLEN / SEG)        // 8
#define WU      384                 // warm-up steps (alpha^384 ~ 3e-9)
#define TILE    32                  // timesteps per smem tile
#define TSTRIDE 36                  // row stride in floats (144B, 16B-aligned; stride%32==4 -> LDS.128 conflict-free)

#define CP_ASYNC16(dst, src) \
    asm volatile("cp.async.cg.shared.global [%0], [%1], 16;" :: "r"(dst), "l"(src))
#define CP_COMMIT() asm volatile("cp.async.commit_group;")

__device__ __forceinline__ uint32_t smem_u32(const void* p) {
    return (uint32_t)__cvta_generic_to_shared(p);
}

// ---------------------------------------------------------------------------
// Kernel 1: causal convs (UNCHANGED from validated round 4/5 — u bitwise same)
// ---------------------------------------------------------------------------
__global__ void __launch_bounds__(256) conv_kernel(
    const float* __restrict__ x,
    const float* __restrict__ w8,
    const float* __restrict__ w16,
    const float* __restrict__ w32,
    float* __restrict__ u)
{
    __shared__ float xs[32][97];
    __shared__ float sw8[8], sw16[16], sw32[32];

    const int tx  = threadIdx.x;
    const int ty  = threadIdx.y;
    const int tid = ty * 8 + tx;
    const int t0  = blockIdx.x * 64;
    const int b0  = blockIdx.y * 32;
    const int warp = tid >> 5;
    const int lane = tid & 31;

    if (tid < 8)       sw8[tid]       = w8[tid];
    else if (tid < 24) sw16[tid - 8]  = w16[tid - 8];
    else if (tid < 56) sw32[tid - 24] = w32[tid - 24];

    {
        const int r0 = warp << 2;
#pragma unroll
        for (int rr = 0; rr < 4; rr++) {
            const float* xrow = x + (size_t)(b0 + r0 + rr) * TLEN;
#pragma unroll
            for (int seg = 0; seg < 3; seg++) {
                int i = (seg << 5) + lane;
                int t = t0 - 32 + i;
                xs[r0 + rr][i] = (t >= 0) ? xrow[t] : 0.0f;
            }
        }
    }
    __syncthreads();

    float xw[39];
#pragma unroll
    for (int j = 0; j < 39; j++) xw[j] = xs[ty][(tx << 3) + 1 + j];

    float a8[8], a16[8], a32[8];
#pragma unroll
    for (int i = 0; i < 8; i++) { a8[i] = 0.f; a16[i] = 0.f; a32[i] = 0.f; }

#pragma unroll
    for (int j = 0; j < 32; j++) {
        float w = sw32[j];
#pragma unroll
        for (int i = 0; i < 8; i++) a32[i] = fmaf(w, xw[i + j], a32[i]);
    }
#pragma unroll
    for (int j = 0; j < 16; j++) {
        float w = sw16[j];
#pragma unroll
        for (int i = 0; i < 8; i++) a16[i] = fmaf(w, xw[16 + i + j], a16[i]);
    }
#pragma unroll
    for (int j = 0; j < 8; j++) {
        float w = sw8[j];
#pragma unroll
        for (int i = 0; i < 8; i++) a8[i] = fmaf(w, xw[24 + i + j], a8[i]);
    }

    float* ub = u + ((size_t)(b0 + ty) * 3) * TLEN + t0 + (tx << 3);
    reinterpret_cast<float4*>(ub + 0 * TLEN)[0] = make_float4(a8[0],  a8[1],  a8[2],  a8[3]);
    reinterpret_cast<float4*>(ub + 0 * TLEN)[1] = make_float4(a8[4],  a8[5],  a8[6],  a8[7]);
    reinterpret_cast<float4*>(ub + 1 * TLEN)[0] = make_float4(a16[0], a16[1], a16[2], a16[3]);
    reinterpret_cast<float4*>(ub + 1 * TLEN)[1] = make_float4(a16[4], a16[5], a16[6], a16[7]);
    reinterpret_cast<float4*>(ub + 2 * TLEN)[0] = make_float4(a32[0], a32[1], a32[2], a32[3]);
    reinterpret_cast<float4*>(ub + 2 * TLEN)[1] = make_float4(a32[4], a32[5], a32[6], a32[7]);
}

// ---------------------------------------------------------------------------
// LIF + WTA step — decision logic IDENTICAL to validated rounds 1-5.
// ---------------------------------------------------------------------------
__device__ __forceinline__ void lif_step_s(float u0, float u1, float u2,
                                           float& v0, float& v1, float& v2,
                                           float& s0, float& s1, float& s2)
{
    float w0 = fmaf(ALPHA_C, v0, u0);
    float w1 = fmaf(ALPHA_C, v1, u1);
    float w2 = fmaf(ALPHA_C, v2, u2);
    float m0 = w0 - THETA_C;
    float m1 = w1 - THETA_C;
    float m2 = w2 - THETA_C;
    float best = fmaxf(m0, fmaxf(m1, m2));
    bool fire = (best >= 0.0f);
    bool t0 = (m0 == best);
    bool t1 = (m1 == best);
    bool e0 = fire && t0;
    bool e1 = fire && t1 && !t0;
    bool e2 = fire && !t0 && !t1;
    s0 = e0 ? 1.0f : 0.0f;
    s1 = e1 ? 1.0f : 0.0f;
    s2 = e2 ? 1.0f : 0.0f;
    v0 = e0 ? m0 : w0;
    v1 = e1 ? m1 : w1;
    v2 = e2 ? m2 : w2;
}

// ---------------------------------------------------------------------------
// Kernel 2: fused LIF scan, cp.async staging, row-major smem (no transpose).
// buf[slot][k][row][TSTRIDE]; thread = row. Spikes written back in place.
// ---------------------------------------------------------------------------
__global__ void __launch_bounds__(64, 4) scan_fused(
    const float* __restrict__ u, float* __restrict__ s)
{
    __shared__ float buf[2][3][ROWS_PB][TSTRIDE];

    const int tid = threadIdx.x;              // 0..63
    const int b0  = blockIdx.x * ROWS_PB;
    const int seg = blockIdx.y;

    const int t_out0   = seg * SEG;
    const int t_begin  = (seg == 0) ? 0 : (t_out0 - WU);
    const int ntiles   = (t_out0 + SEG - t_begin) / TILE;   // 16 or 28
    const int wu_tiles = (t_out0 - t_begin) / TILE;         // 0 or 12

    // task decomposition: p = tid + 64*i, i<24 -> (k, row, f4)
    //   k = p >> 9 ; row = (p >> 3) & 63 ; f4 = p & 7
    // tile bytes: 3*64*32*4 = 24KB, 16B per task.

    // prologue: stage tile 0
    {
        int tt = t_begin;
#pragma unroll
        for (int i = 0; i < 24; i++) {
            int p = tid + (i << 6);
            int k = p >> 9, row = (p >> 3) & 63, f4 = p & 7;
            uint32_t dst = smem_u32(&buf[0][k][row][f4 << 2]);
            const float* src = u + ((size_t)(b0 + row) * 3 + k) * TLEN + tt + (f4 << 2);
            CP_ASYNC16(dst, src);
        }
        CP_COMMIT();
    }

    float v0 = 0.f, v1 = 0.f, v2 = 0.f;

#pragma unroll 1
    for (int ti = 0; ti < ntiles; ti++) {
        const int cur = ti & 1;
        const bool has_next = (ti + 1 < ntiles);
        const bool emit = (ti >= wu_tiles);

        // stage next tile into other buffer (async, in flight during compute)
        if (has_next) {
            int tt = t_begin + (ti + 1) * TILE;
#pragma unroll
            for (int i = 0; i < 24; i++) {
                int p = tid + (i << 6);
                int k = p >> 9, row = (p >> 3) & 63, f4 = p & 7;
                uint32_t dst = smem_u32(&buf[cur ^ 1][k][row][f4 << 2]);
                const float* src = u + ((size_t)(b0 + row) * 3 + k) * TLEN + tt + (f4 << 2);
                CP_ASYNC16(dst, src);
            }
            CP_COMMIT();
            asm volatile("cp.async.wait_group 1;");   // tile ti complete
        } else {
            asm volatile("cp.async.wait_group 0;");
        }
        __syncthreads();

        // compute 32 steps on own row; LDS.128 stride-36 conflict-free
        if (emit) {
#pragma unroll
            for (int t4 = 0; t4 < 8; t4++) {
                float4 c0 = *reinterpret_cast<float4*>(&buf[cur][0][tid][t4 << 2]);
                float4 c1 = *reinterpret_cast<float4*>(&buf[cur][1][tid][t4 << 2]);
                float4 c2 = *reinterpret_cast<float4*>(&buf[cur][2][tid][t4 << 2]);
                float4 o0, o1, o2;
                lif_step_s(c0.x, c1.x, c2.x, v0, v1, v2, o0.x, o1.x, o2.x);
                lif_step_s(c0.y, c1.y, c2.y, v0, v1, v2, o0.y, o1.y, o2.y);
                lif_step_s(c0.z, c1.z, c2.z, v0, v1, v2, o0.z, o1.z, o2.z);
                lif_step_s(c0.w, c1.w, c2.w, v0, v1, v2, o0.w, o1.w, o2.w);
                *reinterpret_cast<float4*>(&buf[cur][0][tid][t4 << 2]) = o0;
                *reinterpret_cast<float4*>(&buf[cur][1][tid][t4 << 2]) = o1;
                *reinterpret_cast<float4*>(&buf[cur][2][tid][t4 << 2]) = o2;
            }
        } else {
#pragma unroll
            for (int t4 = 0; t4 < 8; t4++) {
                float4 c0 = *reinterpret_cast<float4*>(&buf[cur][0][tid][t4 << 2]);
                float4 c1 = *reinterpret_cast<float4*>(&buf[cur][1][tid][t4 << 2]);
                float4 c2 = *reinterpret_cast<float4*>(&buf[cur][2][tid][t4 << 2]);
                float4 o0, o1, o2;
                lif_step_s(c0.x, c1.x, c2.x, v0, v1, v2, o0.x, o1.x, o2.x);
                lif_step_s(c0.y, c1.y, c2.y, v0, v1, v2, o0.y, o1.y, o2.y);
                lif_step_s(c0.z, c1.z, c2.z, v0, v1, v2, o0.z, o1.z, o2.z);
                lif_step_s(c0.w, c1.w, c2.w, v0, v1, v2, o0.w, o1.w, o2.w);
            }
        }

        if (emit) {
            __syncthreads();     // spikes visible to all threads
            int tt = t_begin + ti * TILE;
#pragma unroll
            for (int i = 0; i < 24; i++) {
                int p = tid + (i << 6);
                int k = p >> 9, row = (p >> 3) & 63, f4 = p & 7;
                float4 o = *reinterpret_cast<float4*>(&buf[cur][k][row][f4 << 2]);
                *reinterpret_cast<float4*>(
                    s + ((size_t)(b0 + row) * 3 + k) * TLEN + tt + (f4 << 2)) = o;
            }
        }
        __syncthreads();         // buf[cur] free for re-staging next iteration
    }
}

// ---------------------------------------------------------------------------
extern "C" void kernel_launch(void* const* d_in, const int* in_sizes, int n_in,
                              void* d_out, int out_size)
{
    const float* x   = (const float*)d_in[0];
    const float* w8  = (const float*)d_in[1];
    const float* w16 = (const float*)d_in[2];
    const float* w32 = (const float*)d_in[3];

    float* u = (float*)d_out;
    float* s = u + (size_t)BATCH * 3 * TLEN;

    conv_kernel<<<dim3(TLEN / 64, BATCH / 32), dim3(8, 32)>>>(x, w8, w16, w32, u);
    scan_fused<<<dim3(BATCH / ROWS_PB, NSEG), 64>>>(u, s);
}